// round 7
// baseline (speedup 1.0000x reference)
#include <cuda_runtime.h>
#include <cstdint>

// SparseConv3d as implicit GEMM via mma.sync tf32 m16n8k8.
// B=2 CI=32 CO=64 K=3 96^3, SAME pad, mask epilogue.
// CTA: M=256 spatial positions x N=64 co. 8 warps, each 32x64.

#define NV      96
#define NV2     (NV*NV)
#define CI_     32
#define CO_     64
#define ROWW    98
#define PLANE_Q (NV*ROWW)        // 9408
#define MT      256
#define NTILES  37               // ceil(9408/256)
#define S_STR   456              // 456 mod 32 == 8 -> conflict-free A frags
#define EP_STR  66
#define SMEM_SZ ((CI_*S_STR + CO_) * 4)

// weight fragments: [tap][lane][ks(4)][nt(8)] float2 (b0=W[co][ci_lo], b1=W[co][ci_hi])
__device__ float2 g_wfrag[27 * 32 * 4 * 8];

__device__ __forceinline__ uint32_t f2tf32(float f) {
    uint32_t r; asm("cvt.rna.tf32.f32 %0, %1;" : "=r"(r) : "f"(f)); return r;
}

extern "C" __global__ void wprep_kernel(const float* __restrict__ wgt) {
    int idx = blockIdx.x * 256 + threadIdx.x;          // float2 index
    if (idx >= 27 * 32 * 4 * 8) return;
    int nt   = idx & 7;
    int ks   = (idx >> 3) & 3;
    int lane = (idx >> 5) & 31;
    int tap  = idx >> 10;
    int g = lane >> 2, t = lane & 3;
    int co  = nt * 8 + g;
    int ci0 = ks * 8 + t;
    int ci1 = ci0 + 4;
    float2 v;
    v.x = __uint_as_float(f2tf32(wgt[(co * CI_ + ci0) * 27 + tap]));
    v.y = __uint_as_float(f2tf32(wgt[(co * CI_ + ci1) * 27 + tap]));
    g_wfrag[idx] = v;
}

extern "C" __global__ void __launch_bounds__(256, 2)
conv_mma_kernel(const float* __restrict__ x, const int* __restrict__ mask,
                const float* __restrict__ bias, float* __restrict__ out)
{
    extern __shared__ float smem[];
    float* scratch = smem;                  // [32][456]
    float* bs      = smem + CI_ * S_STR;    // [64]
    const uint32_t* scr_u = (const uint32_t*)scratch;

    const int tid  = threadIdx.x;
    const int w    = tid >> 5;
    const int lane = tid & 31;
    const int g    = lane >> 2;
    const int t    = lane & 3;

    const int tile = blockIdx.x;
    const int pz   = blockIdx.y;            // b*96 + d
    const int b = pz / NV, d = pz % NV;
    const int q0   = tile * MT;
    const int q_lo = q0 - 99;
    const int warp_m = w * 32;

    if (tid < CO_) bs[tid] = bias[tid];

    float acc[2][8][4];
    #pragma unroll
    for (int mt = 0; mt < 2; mt++)
        #pragma unroll
        for (int nt = 0; nt < 8; nt++)
            #pragma unroll
            for (int c = 0; c < 4; c++) acc[mt][nt][c] = 0.0f;

    const float2* wlane = g_wfrag + (size_t)lane * 32;   // + tap*1024 + ks*8 + nt

    for (int dz = 0; dz < 3; dz++) {
        const int dcur = d + dz - 1;
        const bool dok = ((unsigned)dcur < (unsigned)NV);
        __syncthreads();   // everyone done reading previous plane

        // ---- division-free fill: thread (ci = tid>>3) walks s = (tid&7) + 8j ----
        {
            const int ci = tid >> 3;
            int s  = tid & 7;
            int qg = q_lo + s;
            int hh = (qg + 196) / 98 - 2;          // exact floor for qg >= -99
            int ww = qg - hh * ROWW;
            const float* xp = x + ((size_t)(b * CI_ + ci) * NV + (dok ? dcur : 0)) * NV2;
            float* sp = scratch + ci * S_STR;
            #pragma unroll 1
            for (int j = 0; j < 57; j++) {
                float v = 0.0f;
                if (dok && (unsigned)hh < (unsigned)NV && ww < NV)
                    v = xp[hh * NV + ww];
                sp[s] = __uint_as_float(f2tf32(v));
                s += 8; ww += 8;
                if (ww >= ROWW) { ww -= ROWW; hh++; }
            }
        }
        __syncthreads();

        for (int kh = 0; kh < 3; kh++) {
            for (int kw = 0; kw < 3; kw++) {
                const int tap   = dz * 9 + kh * 3 + kw;
                const int sbase = 99 + (kh - 1) * ROWW + (kw - 1) + warp_m;
                const float2* wt = wlane + (size_t)tap * 1024;

                #pragma unroll
                for (int ks = 0; ks < 4; ks++) {
                    float2 bf[8];
                    #pragma unroll
                    for (int nt = 0; nt < 8; nt++) bf[nt] = wt[ks * 8 + nt];

                    uint32_t a[2][4];
                    #pragma unroll
                    for (int mt = 0; mt < 2; mt++) {
                        const int mrow = sbase + mt * 16 + g;
                        const int cib  = ks * 8 + t;
                        a[mt][0] = scr_u[cib * S_STR + mrow];
                        a[mt][1] = scr_u[cib * S_STR + mrow + 8];
                        a[mt][2] = scr_u[(cib + 4) * S_STR + mrow];
                        a[mt][3] = scr_u[(cib + 4) * S_STR + mrow + 8];
                    }
                    #pragma unroll
                    for (int nt = 0; nt < 8; nt++) {
                        #pragma unroll
                        for (int mt = 0; mt < 2; mt++) {
                            asm volatile(
                                "mma.sync.aligned.m16n8k8.row.col.f32.tf32.tf32.f32 "
                                "{%0,%1,%2,%3}, {%4,%5,%6,%7}, {%8,%9}, {%0,%1,%2,%3};\n"
                                : "+f"(acc[mt][nt][0]), "+f"(acc[mt][nt][1]),
                                  "+f"(acc[mt][nt][2]), "+f"(acc[mt][nt][3])
                                : "r"(a[mt][0]), "r"(a[mt][1]), "r"(a[mt][2]), "r"(a[mt][3]),
                                  "r"(__float_as_uint(bf[nt].x)), "r"(__float_as_uint(bf[nt].y)));
                        }
                    }
                }
            }
        }
    }

    // ---- epilogue: two 128-row passes through smem transpose, coalesced stores ----
    float* ep = scratch;   // [128][66]
    #pragma unroll 1
    for (int pass = 0; pass < 2; pass++) {
        __syncthreads();   // prior use of scratch done
        if ((w >> 2) == pass) {
            const int wl = w & 3;
            #pragma unroll
            for (int mt = 0; mt < 2; mt++) {
                #pragma unroll
                for (int nt = 0; nt < 8; nt++) {
                    int m  = wl * 32 + mt * 16 + g;
                    int co = nt * 8 + 2 * t;
                    *(float2*)(ep + m * EP_STR + co) =
                        make_float2(acc[mt][nt][0], acc[mt][nt][1]);
                    *(float2*)(ep + (m + 8) * EP_STR + co) =
                        make_float2(acc[mt][nt][2], acc[mt][nt][3]);
                }
            }
        }
        __syncthreads();

        const int mg0 = pass * 128;
        #pragma unroll
        for (int it = 0; it < 4; it++) {
            int m  = it * 32 + lane;
            int q  = q0 + mg0 + m;
            int hh = q / ROWW;
            int ww = q - hh * ROWW;
            bool ok = (q < PLANE_Q) && (ww < NV);
            int sp  = hh * NV + ww;
            float mval = 0.0f;
            if (ok) mval = (float)mask[(size_t)pz * NV2 + sp];
            #pragma unroll
            for (int j = 0; j < 8; j++) {
                int co = w * 8 + j;
                if (ok)
                    out[((size_t)(b * CO_ + co) * NV + d) * NV2 + sp] =
                        (ep[m * EP_STR + co] + bs[co]) * mval;
            }
        }
    }
}

extern "C" void kernel_launch(void* const* d_in, const int* in_sizes, int n_in,
                              void* d_out, int out_size)
{
    const float* x    = (const float*)d_in[0];
    const int*   mask = (const int*)  d_in[1];
    const float* wgt  = (const float*)d_in[2];
    const float* bias = (const float*)d_in[3];
    float* out = (float*)d_out;

    cudaFuncSetAttribute(conv_mma_kernel,
                         cudaFuncAttributeMaxDynamicSharedMemorySize, SMEM_SZ);

    wprep_kernel<<<(27 * 32 * 4 * 8 + 255) / 256, 256>>>(wgt);

    dim3 grid(NTILES, 2 * NV);   // (37, 192)
    conv_mma_kernel<<<grid, 256, SMEM_SZ>>>(x, mask, bias, out);
}

// round 8
// speedup vs baseline: 1.4523x; 1.4523x over previous
#include <cuda_runtime.h>
#include <cstdint>

// SparseConv3d as implicit GEMM via mma.sync tf32 m16n8k8.
// CTA: M=256 spatial x N=64 co, 512 threads, 16 warps of 32x32 tiles.

#define NV      96
#define NV2     (NV*NV)
#define CI_     32
#define CO_     64
#define ROWW    98
#define PLANE_Q (NV*ROWW)        // 9408
#define MT      256
#define NTILES  37
#define S_STR   456              // mod 32 == 8 -> conflict-free A frags
#define S_ROWS  456
#define EP_STR  66
#define SMEM_SZ ((CI_*S_STR + CO_) * 4)

// B fragments: [tap][nh(2)][lane(32)][ks(4)*nt(4)] float2
__device__ float2 g_wfrag[27 * 2 * 32 * 16];

__device__ __forceinline__ uint32_t f2tf32(float f) {
    uint32_t r; asm("cvt.rna.tf32.f32 %0, %1;" : "=r"(r) : "f"(f)); return r;
}

extern "C" __global__ void wprep_kernel(const float* __restrict__ wgt) {
    int idx = blockIdx.x * 256 + threadIdx.x;   // float2 index
    if (idx >= 27 * 2 * 32 * 16) return;
    int nt   = idx & 3;
    int ks   = (idx >> 2) & 3;
    int lane = (idx >> 4) & 31;
    int nh   = (idx >> 9) & 1;
    int tap  = idx >> 10;
    int g = lane >> 2, t = lane & 3;
    int co  = nh * 32 + nt * 8 + g;
    int ci0 = ks * 8 + t;
    float2 v;
    v.x = __uint_as_float(f2tf32(wgt[(co * CI_ + ci0)     * 27 + tap]));
    v.y = __uint_as_float(f2tf32(wgt[(co * CI_ + ci0 + 4) * 27 + tap]));
    g_wfrag[idx] = v;
}

extern "C" __global__ void __launch_bounds__(512, 1)
conv_mma_kernel(const float* __restrict__ x, const int* __restrict__ mask,
                const float* __restrict__ bias, float* __restrict__ out)
{
    extern __shared__ float smem[];
    float* scratch = smem;                  // [32][456]
    float* bs      = smem + CI_ * S_STR;
    const uint32_t* scr_u = (const uint32_t*)scratch;

    const int tid  = threadIdx.x;
    const int w    = tid >> 5;
    const int lane = tid & 31;
    const int g    = lane >> 2;
    const int t    = lane & 3;

    const int pz = blockIdx.y;              // b*96 + d
    const int b = pz / NV, d = pz % NV;
    const int q0   = blockIdx.x * MT;
    const int q_lo = q0 - 99;

    const int wm = w & 7;                   // m-tile 0..7
    const int nh = w >> 3;                  // n-half 0..1
    const int warp_m = wm * 32;

    if (tid < CO_) bs[tid] = bias[tid];

    float acc[2][4][4];
    #pragma unroll
    for (int mt = 0; mt < 2; mt++)
        #pragma unroll
        for (int nt = 0; nt < 4; nt++)
            #pragma unroll
            for (int c = 0; c < 4; c++) acc[mt][nt][c] = 0.0f;

    // per-lane contiguous B fragment base: 16 float2 per (tap) for this lane/nh
    const float2* wlane = g_wfrag + ((size_t)nh * 32 + lane) * 16;

    for (int dz = 0; dz < 3; dz++) {
        const int dcur = d + dz - 1;
        const bool dok = ((unsigned)dcur < (unsigned)NV);
        __syncthreads();

        // ---- division-free fill: ci = tid>>4, s walks (tid&15)+16j ----
        {
            const int ci = tid >> 4;
            int s  = tid & 15;
            int qg = q_lo + s;
            int hh = (qg + 196) / 98 - 2;       // exact floor, qg >= -99
            int ww = qg - hh * ROWW;
            const float* xp = x + ((size_t)(b * CI_ + ci) * NV + (dok ? dcur : 0)) * NV2;
            float* sp = scratch + ci * S_STR;
            #pragma unroll 1
            for (; s < S_ROWS; s += 16) {
                float v = 0.0f;
                if (dok && (unsigned)hh < (unsigned)NV && ww < NV)
                    v = xp[hh * NV + ww];
                sp[s] = __uint_as_float(f2tf32(v));
                ww += 16;
                if (ww >= ROWW) { ww -= ROWW; hh++; }
            }
        }
        __syncthreads();

        for (int kh = 0; kh < 3; kh++) {
            for (int kw = 0; kw < 3; kw++) {
                const int tap   = dz * 9 + kh * 3 + kw;
                const int sbase = 99 + (kh - 1) * ROWW + (kw - 1) + warp_m;
                const float4* wp = (const float4*)(wlane + (size_t)tap * 1024);

                #pragma unroll
                for (int ks = 0; ks < 4; ks++) {
                    // B: 2 x LDG.128 (L1-resident)
                    float4 u0 = wp[ks * 2 + 0];
                    float4 u1 = wp[ks * 2 + 1];

                    // A: 8 conflict-free LDS
                    const int cib = ks * 8 + t;
                    uint32_t a[2][4];
                    #pragma unroll
                    for (int mt = 0; mt < 2; mt++) {
                        const int mrow = sbase + mt * 16 + g;
                        a[mt][0] = scr_u[cib * S_STR + mrow];
                        a[mt][1] = scr_u[cib * S_STR + mrow + 8];
                        a[mt][2] = scr_u[(cib + 4) * S_STR + mrow];
                        a[mt][3] = scr_u[(cib + 4) * S_STR + mrow + 8];
                    }

                    uint32_t bb[4][2] = {
                        {__float_as_uint(u0.x), __float_as_uint(u0.y)},
                        {__float_as_uint(u0.z), __float_as_uint(u0.w)},
                        {__float_as_uint(u1.x), __float_as_uint(u1.y)},
                        {__float_as_uint(u1.z), __float_as_uint(u1.w)}};

                    #pragma unroll
                    for (int nt = 0; nt < 4; nt++)
                        #pragma unroll
                        for (int mt = 0; mt < 2; mt++)
                            asm volatile(
                                "mma.sync.aligned.m16n8k8.row.col.f32.tf32.tf32.f32 "
                                "{%0,%1,%2,%3}, {%4,%5,%6,%7}, {%8,%9}, {%0,%1,%2,%3};\n"
                                : "+f"(acc[mt][nt][0]), "+f"(acc[mt][nt][1]),
                                  "+f"(acc[mt][nt][2]), "+f"(acc[mt][nt][3])
                                : "r"(a[mt][0]), "r"(a[mt][1]), "r"(a[mt][2]), "r"(a[mt][3]),
                                  "r"(bb[nt][0]), "r"(bb[nt][1]));
                }
            }
        }
    }

    // ---- epilogue: two 128-row passes via smem transpose, coalesced stores ----
    float* ep = scratch;   // [128][66]
    #pragma unroll 1
    for (int pass = 0; pass < 2; pass++) {
        __syncthreads();
        if ((wm >> 2) == pass) {
            #pragma unroll
            for (int mt = 0; mt < 2; mt++) {
                #pragma unroll
                for (int nt = 0; nt < 4; nt++) {
                    int m  = (wm & 3) * 32 + mt * 16 + g;
                    int co = nh * 32 + nt * 8 + 2 * t;
                    *(float2*)(ep + m * EP_STR + co) =
                        make_float2(acc[mt][nt][0], acc[mt][nt][1]);
                    *(float2*)(ep + (m + 8) * EP_STR + co) =
                        make_float2(acc[mt][nt][2], acc[mt][nt][3]);
                }
            }
        }
        __syncthreads();

        const int mg0 = pass * 128;
        #pragma unroll
        for (int it = 0; it < 4; it++) {
            int m  = it * 32 + lane;
            int q  = q0 + mg0 + m;
            int hh = q / ROWW;
            int ww = q - hh * ROWW;
            bool ok = (q < PLANE_Q) && (ww < NV);
            int sp  = hh * NV + ww;
            float mval = 0.0f;
            if (ok) mval = (float)mask[(size_t)pz * NV2 + sp];
            #pragma unroll
            for (int j = 0; j < 4; j++) {
                int co = w * 4 + j;
                if (ok)
                    out[((size_t)(b * CO_ + co) * NV + d) * NV2 + sp] =
                        (ep[m * EP_STR + co] + bs[co]) * mval;
            }
        }
    }
}

extern "C" void kernel_launch(void* const* d_in, const int* in_sizes, int n_in,
                              void* d_out, int out_size)
{
    const float* x    = (const float*)d_in[0];
    const int*   mask = (const int*)  d_in[1];
    const float* wgt  = (const float*)d_in[2];
    const float* bias = (const float*)d_in[3];
    float* out = (float*)d_out;

    cudaFuncSetAttribute(conv_mma_kernel,
                         cudaFuncAttributeMaxDynamicSharedMemorySize, SMEM_SZ);

    wprep_kernel<<<(27 * 2 * 32 * 16 + 255) / 256, 256>>>(wgt);

    dim3 grid(NTILES, 2 * NV);   // (37, 192)
    conv_mma_kernel<<<grid, 512, SMEM_SZ>>>(x, mask, bias, out);
}

// round 9
// speedup vs baseline: 1.4609x; 1.0059x over previous
#include <cuda_runtime.h>
#include <cstdint>

// SparseConv3d as implicit GEMM via mma.sync tf32 m16n8k8.
// CTA: M=256 spatial x N=64 co, 512 threads, 16 warps (8M x 2N) of 32x32 tiles.

#define NV      96
#define NV2     (NV*NV)
#define CI_     32
#define CO_     64
#define ROWW    98
#define PLANE_Q (NV*ROWW)        // 9408
#define MT      256
#define NTILES  37
#define S_STR   456              // mod 32 == 8 -> conflict-free A frags
#define S_ROWS  456
#define EP_STR  66
#define SMEM_SZ ((CI_*S_STR + CO_) * 4)

// B fragments: [tap][nh(2)][lane(32)][ks(4)*nt(4)] float2
__device__ float2 g_wfrag[27 * 2 * 32 * 16];

__device__ __forceinline__ uint32_t f2tf32(float f) {
    uint32_t r; asm("cvt.rna.tf32.f32 %0, %1;" : "=r"(r) : "f"(f)); return r;
}

extern "C" __global__ void wprep_kernel(const float* __restrict__ wgt) {
    int idx = blockIdx.x * 256 + threadIdx.x;   // float2 index
    if (idx >= 27 * 2 * 32 * 16) return;
    int nt   = idx & 3;
    int ks   = (idx >> 2) & 3;
    int lane = (idx >> 4) & 31;
    int nh   = (idx >> 9) & 1;
    int tap  = idx >> 10;
    int g = lane >> 2, t = lane & 3;
    int co  = nh * 32 + nt * 8 + g;
    int ci0 = ks * 8 + t;
    float2 v;
    v.x = __uint_as_float(f2tf32(wgt[(co * CI_ + ci0)     * 27 + tap]));
    v.y = __uint_as_float(f2tf32(wgt[(co * CI_ + ci0 + 4) * 27 + tap]));
    g_wfrag[idx] = v;
}

extern "C" __global__ void __launch_bounds__(512, 1)
conv_mma_kernel(const float* __restrict__ x, const int* __restrict__ mask,
                const float* __restrict__ bias, float* __restrict__ out)
{
    extern __shared__ float smem[];
    float* scratch = smem;                  // [32][456]
    float* bs      = smem + CI_ * S_STR;
    const uint32_t* scr_u = (const uint32_t*)scratch;

    const int tid  = threadIdx.x;
    const int w    = tid >> 5;
    const int lane = tid & 31;
    const int g    = lane >> 2;
    const int t    = lane & 3;

    const int pz = blockIdx.y;              // b*96 + d
    const int b = pz / NV, d = pz % NV;
    const int q0   = blockIdx.x * MT;
    const int q_lo = q0 - 99;

    const int wm = w & 7;                   // m-tile 0..7
    const int nh = w >> 3;                  // n-half 0..1
    const int warp_m = wm * 32;

    if (tid < CO_) bs[tid] = bias[tid];

    float acc[2][4][4];
    #pragma unroll
    for (int mt = 0; mt < 2; mt++)
        #pragma unroll
        for (int nt = 0; nt < 4; nt++)
            #pragma unroll
            for (int c = 0; c < 4; c++) acc[mt][nt][c] = 0.0f;

    // per-lane contiguous B fragments: 16 float2 per tap for this (nh, lane)
    const float2* wlane = g_wfrag + ((size_t)nh * 32 + lane) * 16;

    for (int dz = 0; dz < 3; dz++) {
        const int dcur = d + dz - 1;
        const bool dok = ((unsigned)dcur < (unsigned)NV);
        __syncthreads();

        // ---- division-free fill: ci = tid>>4, s walks (tid&15)+16j ----
        {
            const int ci = tid >> 4;
            int s  = tid & 15;
            int qg = q_lo + s;
            int hh = (qg + 196) / 98 - 2;       // exact floor, qg >= -99
            int ww = qg - hh * ROWW;
            const float* xp = x + ((size_t)(b * CI_ + ci) * NV + (dok ? dcur : 0)) * NV2;
            float* sp = scratch + ci * S_STR;
            #pragma unroll 1
            for (; s < S_ROWS; s += 16) {
                float v = 0.0f;
                if (dok && (unsigned)hh < (unsigned)NV && ww < NV)
                    v = xp[hh * NV + ww];
                sp[s] = __uint_as_float(f2tf32(v));
                ww += 16;
                if (ww >= ROWW) { ww -= ROWW; hh++; }
            }
        }
        __syncthreads();

        #pragma unroll 1
        for (int kh = 0; kh < 3; kh++) {
            #pragma unroll 1
            for (int kw = 0; kw < 3; kw++) {
                const int tap   = dz * 9 + kh * 3 + kw;
                const int sbase = 99 + (kh - 1) * ROWW + (kw - 1) + warp_m;

                // ---- B: prefetch all 16 float2 for this tap (coalesced, L1) ----
                float2 bf[4][4];    // [ks][nt]
                {
                    const float4* wp = (const float4*)(wlane + (size_t)tap * 1024);
                    #pragma unroll
                    for (int ks = 0; ks < 4; ks++) {
                        float4 u0 = wp[ks * 2 + 0];
                        float4 u1 = wp[ks * 2 + 1];
                        bf[ks][0] = make_float2(u0.x, u0.y);
                        bf[ks][1] = make_float2(u0.z, u0.w);
                        bf[ks][2] = make_float2(u1.x, u1.y);
                        bf[ks][3] = make_float2(u1.z, u1.w);
                    }
                }

                #pragma unroll
                for (int ks = 0; ks < 4; ks++) {
                    const int cib = ks * 8 + t;
                    uint32_t a[2][4];
                    #pragma unroll
                    for (int mt = 0; mt < 2; mt++) {
                        const int mrow = sbase + mt * 16 + g;
                        a[mt][0] = scr_u[cib * S_STR + mrow];
                        a[mt][1] = scr_u[cib * S_STR + mrow + 8];
                        a[mt][2] = scr_u[(cib + 4) * S_STR + mrow];
                        a[mt][3] = scr_u[(cib + 4) * S_STR + mrow + 8];
                    }
                    #pragma unroll
                    for (int nt = 0; nt < 4; nt++)
                        #pragma unroll
                        for (int mt = 0; mt < 2; mt++)
                            asm volatile(
                                "mma.sync.aligned.m16n8k8.row.col.f32.tf32.tf32.f32 "
                                "{%0,%1,%2,%3}, {%4,%5,%6,%7}, {%8,%9}, {%0,%1,%2,%3};\n"
                                : "+f"(acc[mt][nt][0]), "+f"(acc[mt][nt][1]),
                                  "+f"(acc[mt][nt][2]), "+f"(acc[mt][nt][3])
                                : "r"(a[mt][0]), "r"(a[mt][1]), "r"(a[mt][2]), "r"(a[mt][3]),
                                  "r"(__float_as_uint(bf[ks][nt].x)),
                                  "r"(__float_as_uint(bf[ks][nt].y)));
                }
            }
        }
    }

    // ---- epilogue: two 128-row passes via smem transpose, coalesced stores ----
    float* ep = scratch;   // [128][66]
    #pragma unroll 1
    for (int pass = 0; pass < 2; pass++) {
        __syncthreads();
        if ((wm >> 2) == pass) {
            #pragma unroll
            for (int mt = 0; mt < 2; mt++) {
                #pragma unroll
                for (int nt = 0; nt < 4; nt++) {
                    int m  = (wm & 3) * 32 + mt * 16 + g;
                    int co = nh * 32 + nt * 8 + 2 * t;
                    *(float2*)(ep + m * EP_STR + co) =
                        make_float2(acc[mt][nt][0], acc[mt][nt][1]);
                    *(float2*)(ep + (m + 8) * EP_STR + co) =
                        make_float2(acc[mt][nt][2], acc[mt][nt][3]);
                }
            }
        }
        __syncthreads();

        const int mg0 = pass * 128;
        #pragma unroll
        for (int it = 0; it < 4; it++) {
            int m  = it * 32 + lane;
            int q  = q0 + mg0 + m;
            int hh = q / ROWW;
            int ww = q - hh * ROWW;
            bool ok = (q < PLANE_Q) && (ww < NV);
            int sp  = hh * NV + ww;
            float mval = 0.0f;
            if (ok) mval = (float)mask[(size_t)pz * NV2 + sp];
            #pragma unroll
            for (int j = 0; j < 4; j++) {
                int co = w * 4 + j;
                if (ok)
                    out[((size_t)(b * CO_ + co) * NV + d) * NV2 + sp] =
                        (ep[m * EP_STR + co] + bs[co]) * mval;
            }
        }
    }
}

extern "C" void kernel_launch(void* const* d_in, const int* in_sizes, int n_in,
                              void* d_out, int out_size)
{
    const float* x    = (const float*)d_in[0];
    const int*   mask = (const int*)  d_in[1];
    const float* wgt  = (const float*)d_in[2];
    const float* bias = (const float*)d_in[3];
    float* out = (float*)d_out;

    cudaFuncSetAttribute(conv_mma_kernel,
                         cudaFuncAttributeMaxDynamicSharedMemorySize, SMEM_SZ);

    wprep_kernel<<<(27 * 2 * 32 * 16 + 255) / 256, 256>>>(wgt);

    dim3 grid(NTILES, 2 * NV);   // (37, 192)
    conv_mma_kernel<<<grid, 512, SMEM_SZ>>>(x, mask, bias, out);
}

// round 10
// speedup vs baseline: 3.0389x; 2.0802x over previous
#include <cuda_runtime.h>
#include <cstdint>

// SparseConv3d as implicit GEMM via mma.sync tf32 m16n8k8.
// R6 structure (MT=128, 256 thr, 2 CTA/SM, lane-fastest B frags) + div-free fill.

#define NV      96
#define NV2     (NV*NV)
#define CI_     32
#define CO_     64
#define ROWW    98
#define PLANE_Q (NV*ROWW)        // 9408
#define MT      128
#define NTILES  74               // ceil(9408/128)
#define S_STR   328              // mod 32 == 8 -> conflict-free A frags
#define S_ROWS  326
#define EP_STR  66

// weight fragments: [tap][gnt(8)][ks(4)][lane(32)] float2  (lane-fastest!)
__device__ float2 g_wfrag[27 * 8 * 4 * 32];

__device__ __forceinline__ uint32_t f2tf32(float f) {
    uint32_t r; asm("cvt.rna.tf32.f32 %0, %1;" : "=r"(r) : "f"(f)); return r;
}

extern "C" __global__ void wprep_kernel(const float* __restrict__ wgt) {
    int idx = blockIdx.x * 256 + threadIdx.x;   // over 27*8*4*32 float2
    if (idx >= 27 * 8 * 4 * 32) return;
    int lane = idx & 31;
    int r    = idx >> 5;
    int ks   = r & 3;  r >>= 2;
    int gnt  = r & 7;  r >>= 3;
    int tap  = r;
    int g = lane >> 2, t = lane & 3;
    int co  = gnt * 8 + g;
    int ci0 = ks * 8 + t;
    float2 v;
    v.x = __uint_as_float(f2tf32(wgt[(co * CI_ + ci0)     * 27 + tap]));
    v.y = __uint_as_float(f2tf32(wgt[(co * CI_ + ci0 + 4) * 27 + tap]));
    g_wfrag[idx] = v;
}

extern "C" __global__ void __launch_bounds__(256, 2)
conv_mma_kernel(const float* __restrict__ x, const int* __restrict__ mask,
                const float* __restrict__ bias, float* __restrict__ out)
{
    __shared__ float scratch[CI_ * S_STR];   // reused as epilogue [128][66]
    __shared__ float bs[CO_];

    const int tid  = threadIdx.x;
    const int w    = tid >> 5;
    const int lane = tid & 31;
    const int g    = lane >> 2;
    const int t    = lane & 3;

    const int pz = blockIdx.y;               // b*96 + d
    const int b = pz / NV, d = pz % NV;
    const int q0   = blockIdx.x * MT;
    const int q_lo = q0 - 99;

    const int warp_m = (w >> 1) * 32;        // 0,32,64,96
    const int warp_n = (w & 1) * 32;         // 0,32

    if (tid < CO_) bs[tid] = bias[tid];

    float acc[2][4][4];
    #pragma unroll
    for (int mt = 0; mt < 2; mt++)
        #pragma unroll
        for (int nt = 0; nt < 4; nt++)
            #pragma unroll
            for (int c = 0; c < 4; c++) acc[mt][nt][c] = 0.0f;

    const uint32_t* scr_u = (const uint32_t*)scratch;

    for (int dz = 0; dz < 3; dz++) {
        const int dcur = d + dz - 1;
        const bool dok = ((unsigned)dcur < (unsigned)NV);
        __syncthreads();   // all warps done reading previous dz's scratch

        // ---- division-free fill: ci = tid>>3, s walks (tid&7)+8j ----
        {
            const int ci = tid >> 3;
            int s  = tid & 7;
            int qg = q_lo + s;
            int hh = (qg + 196) / 98 - 2;        // one exact floor-div per plane
            int ww = qg - hh * ROWW;
            const float* xp = x + ((size_t)(b * CI_ + ci) * NV + (dok ? dcur : 0)) * NV2;
            float* sp = scratch + ci * S_STR;
            #pragma unroll 1
            for (; s < S_ROWS; s += 8) {
                float v = 0.0f;
                if (dok && (unsigned)hh < (unsigned)NV && ww < NV)
                    v = xp[hh * NV + ww];
                sp[s] = __uint_as_float(f2tf32(v));
                ww += 8;
                if (ww >= ROWW) { ww -= ROWW; hh++; }
            }
        }
        __syncthreads();

        #pragma unroll 1
        for (int kh = 0; kh < 3; kh++) {
            #pragma unroll 1
            for (int kw = 0; kw < 3; kw++) {
                const int tap   = dz * 9 + kh * 3 + kw;
                const int sbase = 99 + (kh - 1) * ROWW + (kw - 1) + warp_m;

                // ---- B fragments: 16 coalesced float2 LDG (lane-fastest, L1) ----
                float2 bf[4][4];
                const float2* wf = g_wfrag + ((size_t)tap * 8 + (w & 1) * 4) * 128 + lane;
                #pragma unroll
                for (int nt = 0; nt < 4; nt++)
                    #pragma unroll
                    for (int ks = 0; ks < 4; ks++)
                        bf[nt][ks] = wf[(nt * 4 + ks) * 32];

                // ---- A fragments from smem + 32 mma ----
                #pragma unroll
                for (int mt = 0; mt < 2; mt++) {
                    const int mrow = sbase + mt * 16 + g;
                    #pragma unroll
                    for (int ks = 0; ks < 4; ks++) {
                        const int cib = ks * 8 + t;
                        uint32_t a0 = scr_u[cib * S_STR + mrow];
                        uint32_t a1 = scr_u[cib * S_STR + mrow + 8];
                        uint32_t a2 = scr_u[(cib + 4) * S_STR + mrow];
                        uint32_t a3 = scr_u[(cib + 4) * S_STR + mrow + 8];
                        #pragma unroll
                        for (int nt = 0; nt < 4; nt++) {
                            uint32_t b0 = __float_as_uint(bf[nt][ks].x);
                            uint32_t b1 = __float_as_uint(bf[nt][ks].y);
                            asm volatile(
                                "mma.sync.aligned.m16n8k8.row.col.f32.tf32.tf32.f32 "
                                "{%0,%1,%2,%3}, {%4,%5,%6,%7}, {%8,%9}, {%0,%1,%2,%3};\n"
                                : "+f"(acc[mt][nt][0]), "+f"(acc[mt][nt][1]),
                                  "+f"(acc[mt][nt][2]), "+f"(acc[mt][nt][3])
                                : "r"(a0), "r"(a1), "r"(a2), "r"(a3), "r"(b0), "r"(b1));
                        }
                    }
                }
            }
        }
    }

    // ---- epilogue: acc -> smem transpose -> coalesced masked stores ----
    __syncthreads();
    float* ep = scratch;             // [128][66]
    #pragma unroll
    for (int mt = 0; mt < 2; mt++) {
        #pragma unroll
        for (int nt = 0; nt < 4; nt++) {
            int m  = warp_m + mt * 16 + g;
            int co = warp_n + nt * 8 + 2 * t;
            *(float2*)(ep + m * EP_STR + co)       = make_float2(acc[mt][nt][0], acc[mt][nt][1]);
            *(float2*)(ep + (m + 8) * EP_STR + co) = make_float2(acc[mt][nt][2], acc[mt][nt][3]);
        }
    }
    __syncthreads();

    #pragma unroll
    for (int it = 0; it < 4; it++) {
        int m  = it * 32 + lane;
        int q  = q0 + m;
        int hh = q / ROWW;
        int ww = q - hh * ROWW;
        bool ok = (q < PLANE_Q) && (ww < NV);
        float mval = 0.0f;
        int sp = hh * NV + ww;
        if (ok) mval = (float)mask[(size_t)pz * NV2 + sp];
        #pragma unroll
        for (int j = 0; j < 8; j++) {
            int co = w * 8 + j;
            if (ok)
                out[((size_t)(b * CO_ + co) * NV + d) * NV2 + sp] =
                    (ep[m * EP_STR + co] + bs[co]) * mval;
        }
    }
}

extern "C" void kernel_launch(void* const* d_in, const int* in_sizes, int n_in,
                              void* d_out, int out_size)
{
    const float* x    = (const float*)d_in[0];
    const int*   mask = (const int*)  d_in[1];
    const float* wgt  = (const float*)d_in[2];
    const float* bias = (const float*)d_in[3];
    float* out = (float*)d_out;

    wprep_kernel<<<(27 * 8 * 4 * 32 + 255) / 256, 256>>>(wgt);

    dim3 grid(NTILES, 2 * NV);   // (74, 192)
    conv_mma_kernel<<<grid, 256>>>(x, mask, bias, out);
}

// round 11
// speedup vs baseline: 3.8717x; 1.2741x over previous
#include <cuda_runtime.h>
#include <cstdint>

// SparseConv3d as implicit GEMM via mma.sync tf32 m16n8k8.
// R10 structure (MT=128, 256 thr, lane-fastest B frags, div-free fill)
// + per-ks B loads (reg trim) + 3 CTAs/SM.

#define NV      96
#define NV2     (NV*NV)
#define CI_     32
#define CO_     64
#define ROWW    98
#define PLANE_Q (NV*ROWW)        // 9408
#define MT      128
#define NTILES  74               // ceil(9408/128)
#define S_STR   328              // mod 32 == 8 -> conflict-free A frags
#define S_ROWS  326
#define EP_STR  66

// weight fragments: [tap][gnt(8)][ks(4)][lane(32)] float2  (lane-fastest)
__device__ float2 g_wfrag[27 * 8 * 4 * 32];

__device__ __forceinline__ uint32_t f2tf32(float f) {
    uint32_t r; asm("cvt.rna.tf32.f32 %0, %1;" : "=r"(r) : "f"(f)); return r;
}

extern "C" __global__ void wprep_kernel(const float* __restrict__ wgt) {
    int idx = blockIdx.x * 256 + threadIdx.x;   // over 27*8*4*32 float2
    if (idx >= 27 * 8 * 4 * 32) return;
    int lane = idx & 31;
    int r    = idx >> 5;
    int ks   = r & 3;  r >>= 2;
    int gnt  = r & 7;  r >>= 3;
    int tap  = r;
    int g = lane >> 2, t = lane & 3;
    int co  = gnt * 8 + g;
    int ci0 = ks * 8 + t;
    float2 v;
    v.x = __uint_as_float(f2tf32(wgt[(co * CI_ + ci0)     * 27 + tap]));
    v.y = __uint_as_float(f2tf32(wgt[(co * CI_ + ci0 + 4) * 27 + tap]));
    g_wfrag[idx] = v;
}

extern "C" __global__ void __launch_bounds__(256, 3)
conv_mma_kernel(const float* __restrict__ x, const int* __restrict__ mask,
                const float* __restrict__ bias, float* __restrict__ out)
{
    __shared__ float scratch[CI_ * S_STR];   // reused as epilogue [128][66]
    __shared__ float bs[CO_];

    const int tid  = threadIdx.x;
    const int w    = tid >> 5;
    const int lane = tid & 31;
    const int g    = lane >> 2;
    const int t    = lane & 3;

    const int pz = blockIdx.y;               // b*96 + d
    const int b = pz / NV, d = pz % NV;
    const int q0   = blockIdx.x * MT;
    const int q_lo = q0 - 99;

    const int warp_m = (w >> 1) * 32;        // 0,32,64,96
    const int warp_n = (w & 1) * 32;         // 0,32

    if (tid < CO_) bs[tid] = bias[tid];

    float acc[2][4][4];
    #pragma unroll
    for (int mt = 0; mt < 2; mt++)
        #pragma unroll
        for (int nt = 0; nt < 4; nt++)
            #pragma unroll
            for (int c = 0; c < 4; c++) acc[mt][nt][c] = 0.0f;

    const uint32_t* scr_u = (const uint32_t*)scratch;

    for (int dz = 0; dz < 3; dz++) {
        const int dcur = d + dz - 1;
        const bool dok = ((unsigned)dcur < (unsigned)NV);
        __syncthreads();   // all warps done reading previous dz's scratch

        // ---- division-free fill: ci = tid>>3, s walks (tid&7)+8j ----
        {
            const int ci = tid >> 3;
            int s  = tid & 7;
            int qg = q_lo + s;
            int hh = (qg + 196) / 98 - 2;        // one exact floor-div per plane
            int ww = qg - hh * ROWW;
            const float* xp = x + ((size_t)(b * CI_ + ci) * NV + (dok ? dcur : 0)) * NV2;
            float* sp = scratch + ci * S_STR;
            #pragma unroll 1
            for (; s < S_ROWS; s += 8) {
                float v = 0.0f;
                if (dok && (unsigned)hh < (unsigned)NV && ww < NV)
                    v = xp[hh * NV + ww];
                sp[s] = __uint_as_float(f2tf32(v));
                ww += 8;
                if (ww >= ROWW) { ww -= ROWW; hh++; }
            }
        }
        __syncthreads();

        #pragma unroll 1
        for (int kh = 0; kh < 3; kh++) {
            #pragma unroll 1
            for (int kw = 0; kw < 3; kw++) {
                const int tap   = dz * 9 + kh * 3 + kw;
                const int sbase = 99 + (kh - 1) * ROWW + (kw - 1) + warp_m;
                const float2* wf = g_wfrag + ((size_t)tap * 8 + (w & 1) * 4) * 128 + lane;

                #pragma unroll
                for (int ks = 0; ks < 4; ks++) {
                    // B: 4 lane-fastest LDG.64 for this ks (L1-resident)
                    float2 bf[4];
                    #pragma unroll
                    for (int nt = 0; nt < 4; nt++)
                        bf[nt] = wf[(nt * 4 + ks) * 32];

                    const int cib = ks * 8 + t;
                    #pragma unroll
                    for (int mt = 0; mt < 2; mt++) {
                        const int mrow = sbase + mt * 16 + g;
                        uint32_t a0 = scr_u[cib * S_STR + mrow];
                        uint32_t a1 = scr_u[cib * S_STR + mrow + 8];
                        uint32_t a2 = scr_u[(cib + 4) * S_STR + mrow];
                        uint32_t a3 = scr_u[(cib + 4) * S_STR + mrow + 8];
                        #pragma unroll
                        for (int nt = 0; nt < 4; nt++) {
                            asm volatile(
                                "mma.sync.aligned.m16n8k8.row.col.f32.tf32.tf32.f32 "
                                "{%0,%1,%2,%3}, {%4,%5,%6,%7}, {%8,%9}, {%0,%1,%2,%3};\n"
                                : "+f"(acc[mt][nt][0]), "+f"(acc[mt][nt][1]),
                                  "+f"(acc[mt][nt][2]), "+f"(acc[mt][nt][3])
                                : "r"(a0), "r"(a1), "r"(a2), "r"(a3),
                                  "r"(__float_as_uint(bf[nt].x)),
                                  "r"(__float_as_uint(bf[nt].y)));
                        }
                    }
                }
            }
        }
    }

    // ---- epilogue: acc -> smem transpose -> coalesced masked stores ----
    __syncthreads();
    float* ep = scratch;             // [128][66]
    #pragma unroll
    for (int mt = 0; mt < 2; mt++) {
        #pragma unroll
        for (int nt = 0; nt < 4; nt++) {
            int m  = warp_m + mt * 16 + g;
            int co = warp_n + nt * 8 + 2 * t;
            *(float2*)(ep + m * EP_STR + co)       = make_float2(acc[mt][nt][0], acc[mt][nt][1]);
            *(float2*)(ep + (m + 8) * EP_STR + co) = make_float2(acc[mt][nt][2], acc[mt][nt][3]);
        }
    }
    __syncthreads();

    #pragma unroll
    for (int it = 0; it < 4; it++) {
        int m  = it * 32 + lane;
        int q  = q0 + m;
        int hh = q / ROWW;
        int ww = q - hh * ROWW;
        bool ok = (q < PLANE_Q) && (ww < NV);
        float mval = 0.0f;
        int sp = hh * NV + ww;
        if (ok) mval = (float)mask[(size_t)pz * NV2 + sp];
        #pragma unroll
        for (int j = 0; j < 8; j++) {
            int co = w * 8 + j;
            if (ok)
                out[((size_t)(b * CO_ + co) * NV + d) * NV2 + sp] =
                    (ep[m * EP_STR + co] + bs[co]) * mval;
        }
    }
}

extern "C" void kernel_launch(void* const* d_in, const int* in_sizes, int n_in,
                              void* d_out, int out_size)
{
    const float* x    = (const float*)d_in[0];
    const int*   mask = (const int*)  d_in[1];
    const float* wgt  = (const float*)d_in[2];
    const float* bias = (const float*)d_in[3];
    float* out = (float*)d_out;

    wprep_kernel<<<(27 * 8 * 4 * 32 + 255) / 256, 256>>>(wgt);

    dim3 grid(NTILES, 2 * NV);   // (74, 192)
    conv_mma_kernel<<<grid, 256>>>(x, mask, bias, out);
}

// round 12
// speedup vs baseline: 4.5755x; 1.1818x over previous
#include <cuda_runtime.h>
#include <cstdint>

// SparseConv3d as implicit GEMM via mma.sync tf32 m16n8k8.
// R11 structure + 4 CTAs/SM (64-reg cap) + hoisted inner-loop addressing.

#define NV      96
#define NV2     (NV*NV)
#define CI_     32
#define CO_     64
#define ROWW    98
#define PLANE_Q (NV*ROWW)        // 9408
#define MT      128
#define NTILES  74               // ceil(9408/128)
#define S_STR   328              // mod 32 == 8 -> conflict-free A frags
#define S_ROWS  326
#define EP_STR  66

// weight fragments: [tap][gnt(8)][ks(4)][lane(32)] float2  (lane-fastest)
__device__ float2 g_wfrag[27 * 8 * 4 * 32];

__device__ __forceinline__ uint32_t f2tf32(float f) {
    uint32_t r; asm("cvt.rna.tf32.f32 %0, %1;" : "=r"(r) : "f"(f)); return r;
}

extern "C" __global__ void wprep_kernel(const float* __restrict__ wgt) {
    int idx = blockIdx.x * 256 + threadIdx.x;   // over 27*8*4*32 float2
    if (idx >= 27 * 8 * 4 * 32) return;
    int lane = idx & 31;
    int r    = idx >> 5;
    int ks   = r & 3;  r >>= 2;
    int gnt  = r & 7;  r >>= 3;
    int tap  = r;
    int g = lane >> 2, t = lane & 3;
    int co  = gnt * 8 + g;
    int ci0 = ks * 8 + t;
    float2 v;
    v.x = __uint_as_float(f2tf32(wgt[(co * CI_ + ci0)     * 27 + tap]));
    v.y = __uint_as_float(f2tf32(wgt[(co * CI_ + ci0 + 4) * 27 + tap]));
    g_wfrag[idx] = v;
}

extern "C" __global__ void __launch_bounds__(256, 4)
conv_mma_kernel(const float* __restrict__ x, const int* __restrict__ mask,
                const float* __restrict__ bias, float* __restrict__ out)
{
    __shared__ float scratch[CI_ * S_STR];   // reused as epilogue [128][66]
    __shared__ float bs[CO_];

    const int tid  = threadIdx.x;
    const int w    = tid >> 5;
    const int lane = tid & 31;
    const int g    = lane >> 2;
    const int t    = lane & 3;

    const int pz = blockIdx.y;               // b*96 + d
    const int b = pz / NV, d = pz % NV;
    const int q0   = blockIdx.x * MT;
    const int q_lo = q0 - 99;

    const int warp_m = (w >> 1) * 32;        // 0,32,64,96
    const int warp_n = (w & 1) * 32;         // 0,32

    if (tid < CO_) bs[tid] = bias[tid];

    float acc[2][4][4];
    #pragma unroll
    for (int mt = 0; mt < 2; mt++)
        #pragma unroll
        for (int nt = 0; nt < 4; nt++)
            #pragma unroll
            for (int c = 0; c < 4; c++) acc[mt][nt][c] = 0.0f;

    // per-(warp,lane) A base inside scratch: row t of K-groups, col offset of this warp
    const uint32_t* scr_u = (const uint32_t*)scratch;
    // B base for this warp half / lane
    const float2* wbase = g_wfrag + (size_t)(w & 1) * 4 * 128 + lane;

    for (int dz = 0; dz < 3; dz++) {
        const int dcur = d + dz - 1;
        const bool dok = ((unsigned)dcur < (unsigned)NV);
        __syncthreads();   // all warps done reading previous dz's scratch

        // ---- division-free fill: ci = tid>>3, s walks (tid&7)+8j ----
        {
            const int ci = tid >> 3;
            int s  = tid & 7;
            int qg = q_lo + s;
            int hh = (qg + 196) / 98 - 2;        // one exact floor-div per plane
            int ww = qg - hh * ROWW;
            const float* xp = x + ((size_t)(b * CI_ + ci) * NV + (dok ? dcur : 0)) * NV2;
            float* sp = scratch + ci * S_STR;
            #pragma unroll 1
            for (; s < S_ROWS; s += 8) {
                float v = 0.0f;
                if (dok && (unsigned)hh < (unsigned)NV && ww < NV)
                    v = xp[hh * NV + ww];
                sp[s] = __uint_as_float(f2tf32(v));
                ww += 8;
                if (ww >= ROWW) { ww -= ROWW; hh++; }
            }
        }
        __syncthreads();

        #pragma unroll 1
        for (int kh = 0; kh < 3; kh++) {
            #pragma unroll 1
            for (int kw = 0; kw < 3; kw++) {
                const int tap   = dz * 9 + kh * 3 + kw;
                const int sbase = 99 + (kh - 1) * ROWW + (kw - 1) + warp_m + g;
                const float2* wf = wbase + (size_t)tap * 1024;
                // base pointer for this thread's A rows (K-group row t)
                const uint32_t* ap = scr_u + (size_t)t * S_STR + sbase;

                #pragma unroll
                for (int ks = 0; ks < 4; ks++) {
                    // B: 4 lane-fastest LDG.64 (L1-resident)
                    float2 bf0 = wf[(0 * 4 + ks) * 32];
                    float2 bf1 = wf[(1 * 4 + ks) * 32];
                    float2 bf2 = wf[(2 * 4 + ks) * 32];
                    float2 bf3 = wf[(3 * 4 + ks) * 32];

                    const uint32_t* a_ks = ap + (size_t)(ks * 8) * S_STR;
                    #pragma unroll
                    for (int mt = 0; mt < 2; mt++) {
                        const uint32_t* am = a_ks + mt * 16;
                        uint32_t a0 = am[0];
                        uint32_t a1 = am[8];
                        uint32_t a2 = am[4 * S_STR];
                        uint32_t a3 = am[4 * S_STR + 8];
                        #pragma unroll
                        for (int nt = 0; nt < 4; nt++) {
                            float2 bv = (nt == 0) ? bf0 : (nt == 1) ? bf1 : (nt == 2) ? bf2 : bf3;
                            asm volatile(
                                "mma.sync.aligned.m16n8k8.row.col.f32.tf32.tf32.f32 "
                                "{%0,%1,%2,%3}, {%4,%5,%6,%7}, {%8,%9}, {%0,%1,%2,%3};\n"
                                : "+f"(acc[mt][nt][0]), "+f"(acc[mt][nt][1]),
                                  "+f"(acc[mt][nt][2]), "+f"(acc[mt][nt][3])
                                : "r"(a0), "r"(a1), "r"(a2), "r"(a3),
                                  "r"(__float_as_uint(bv.x)),
                                  "r"(__float_as_uint(bv.y)));
                        }
                    }
                }
            }
        }
    }

    // ---- epilogue: acc -> smem transpose -> coalesced masked stores ----
    __syncthreads();
    float* ep = scratch;             // [128][66]
    #pragma unroll
    for (int mt = 0; mt < 2; mt++) {
        #pragma unroll
        for (int nt = 0; nt < 4; nt++) {
            int m  = warp_m + mt * 16 + g;
            int co = warp_n + nt * 8 + 2 * t;
            *(float2*)(ep + m * EP_STR + co)       = make_float2(acc[mt][nt][0], acc[mt][nt][1]);
            *(float2*)(ep + (m + 8) * EP_STR + co) = make_float2(acc[mt][nt][2], acc[mt][nt][3]);
        }
    }
    __syncthreads();

    #pragma unroll
    for (int it = 0; it < 4; it++) {
        int m  = it * 32 + lane;
        int q  = q0 + m;
        int hh = q / ROWW;
        int ww = q - hh * ROWW;
        bool ok = (q < PLANE_Q) && (ww < NV);
        float mval = 0.0f;
        int sp = hh * NV + ww;
        if (ok) mval = (float)mask[(size_t)pz * NV2 + sp];
        #pragma unroll
        for (int j = 0; j < 8; j++) {
            int co = w * 8 + j;
            if (ok)
                out[((size_t)(b * CO_ + co) * NV + d) * NV2 + sp] =
                    (ep[m * EP_STR + co] + bs[co]) * mval;
        }
    }
}

extern "C" void kernel_launch(void* const* d_in, const int* in_sizes, int n_in,
                              void* d_out, int out_size)
{
    const float* x    = (const float*)d_in[0];
    const int*   mask = (const int*)  d_in[1];
    const float* wgt  = (const float*)d_in[2];
    const float* bias = (const float*)d_in[3];
    float* out = (float*)d_out;

    wprep_kernel<<<(27 * 8 * 4 * 32 + 255) / 256, 256>>>(wgt);

    dim3 grid(NTILES, 2 * NV);   // (74, 192)
    conv_mma_kernel<<<grid, 256>>>(x, mask, bias, out);
}